// round 7
// baseline (speedup 1.0000x reference)
#include <cuda_runtime.h>
#include <cuda_fp16.h>
#include <cstdint>

#define MAX_ENT   50000
#define MAX_E     1600000
#define MAX_REL   10       // N_REL - 1
#define C_DIM     128
#define C_VEC     (C_DIM / 4)    // 32 float4 per fp32 row
#define C_H2V     (C_DIM / 4)    // 32 uint2 (4 halves) per fp16 row

// ---------------- device scratch (static globals: no allocation allowed) ----
__device__ int            g_is64;
__device__ int            g_head[MAX_E];
__device__ unsigned short g_rank[MAX_E];     // within-head slot from histogram
__device__ unsigned       g_val[MAX_E];      // packed tail | (rel<<20)
__device__ unsigned       g_csr[MAX_E];      // CSR values: packed tail|rel
__device__ int            g_cnt[MAX_ENT];
__device__ int            g_row_start[MAX_ENT + 1];
__device__ uint2          g_embH[MAX_ENT * C_H2V];  // fp16 input embeddings
__device__ uint2          g_embA[MAX_ENT * C_H2V];  // fp16 hop-1 output
__device__ uint2          g_embB[MAX_ENT * C_H2V];  // fp16 hop-2 output

// ---------------------------------------------------------------------------
// 0) fused: zero per-head counters + fp32->fp16 embedding convert + width
//    detection.  (int64 ids < 2^31 have all odd 32-bit words zero; effectively
//    impossible for the int32 interpretation of random ids in [0,50000).)
__global__ void init_convert_kernel(const unsigned* __restrict__ words,
                                    const float4* __restrict__ emb,
                                    int n_ent, int n_vec) {
    int i = blockIdx.x * blockDim.x + threadIdx.x;
    if (i < n_ent) g_cnt[i] = 0;
    if (i < n_vec) {
        float4 f = emb[i];
        __half2 a = __floats2half2_rn(f.x, f.y);
        __half2 b = __floats2half2_rn(f.z, f.w);
        uint2 q;
        q.x = *(unsigned*)&a;
        q.y = *(unsigned*)&b;
        g_embH[i] = q;
    }
    if (i == 0) {
        int is64 = 1;
        #pragma unroll 1
        for (int k = 1; k < 64; k += 2) {     // 32 odd-word checks suffice
            if (words[k] != 0u) { is64 = 0; break; }
        }
        g_is64 = is64;
    }
}

// 1) decode edges, histogram head degrees, record within-head rank
__global__ void build_a_kernel(const void* __restrict__ edge_index,
                               const void* __restrict__ edge_type, int E) {
    int j = blockIdx.x * blockDim.x + threadIdx.x;
    if (j >= E) return;
    int head, tail, rel;
    if (g_is64) {
        const long long* ei = (const long long*)edge_index;
        const long long* et = (const long long*)edge_type;
        head = (int)ei[j];
        tail = (int)ei[E + j];
        rel  = (int)et[j] - 1;
    } else {
        const int* ei = (const int*)edge_index;
        const int* et = (const int*)edge_type;
        head = ei[j];
        tail = ei[E + j];
        rel  = et[j] - 1;
    }
    g_head[j] = head;
    g_val[j]  = (unsigned)tail | ((unsigned)rel << 20);
    int r = atomicAdd(&g_cnt[head], 1);
    g_rank[j] = (unsigned short)r;           // degrees ~Poisson(32) << 65536
}

// 2) exclusive scan of g_cnt -> g_row_start.  Single block, 1024 threads.
__global__ void scan_kernel(int n_ent) {
    __shared__ int ssum[1024];
    const int t    = threadIdx.x;
    const int PER  = (n_ent + 1023) / 1024;
    const int base = t * PER;

    int s = 0;
    for (int i = 0; i < PER; i++) {
        int idx = base + i;
        if (idx < n_ent) s += g_cnt[idx];
    }
    ssum[t] = s;
    __syncthreads();
    for (int off = 1; off < 1024; off <<= 1) {
        int v = (t >= off) ? ssum[t - off] : 0;
        __syncthreads();
        ssum[t] += v;
        __syncthreads();
    }
    int run = ssum[t] - s;
    for (int i = 0; i < PER; i++) {
        int idx = base + i;
        if (idx < n_ent) {
            g_row_start[idx] = run;
            run += g_cnt[idx];
        }
    }
    if (t == 1023) g_row_start[n_ent] = ssum[1023];
}

// 3) fill CSR values -- atomic-free: pos = row_start[head] + rank
__global__ void build_b_kernel(int E) {
    int j = blockIdx.x * blockDim.x + threadIdx.x;
    if (j >= E) return;
    int pos = g_row_start[g_head[j]] + (int)g_rank[j];
    g_csr[pos] = g_val[j];
}

// 4) fused hop: fp16 gather + relation scale + mean + L2-normalize.
//    One warp per entity; CSR entries fetched once per 32-edge batch via a
//    lane-distributed LDG + shfl broadcast; weights fp16 in smem (LDS.64).
//    hop 0: src embH -> dst embA.   hop 1: embA -> embB.
//    hop 2: embB -> res = emb32 + h1 + h2 + h3  (fused finish).
__global__ __launch_bounds__(256)
void hop_kernel(const float4* __restrict__ weight,
                const float4* __restrict__ emb32,
                float4* __restrict__ res,
                int n_ent, int n_rel, int hop) {
    __shared__ uint2 swh[MAX_REL * C_VEC];   // 2.5 KB: fp16 relation rows
    for (int i = threadIdx.x; i < n_rel * C_VEC; i += blockDim.x) {
        float4 w = weight[i];
        __half2 a = __floats2half2_rn(w.x, w.y);
        __half2 b = __floats2half2_rn(w.z, w.w);
        uint2 q;
        q.x = *(unsigned*)&a;
        q.y = *(unsigned*)&b;
        swh[i] = q;
    }
    __syncthreads();

    const uint2* src = (hop == 0) ? (const uint2*)g_embH
                     : (hop == 1) ? (const uint2*)g_embA
                                  : (const uint2*)g_embB;

    int warp = (blockIdx.x * blockDim.x + threadIdx.x) >> 5;
    int lane = threadIdx.x & 31;
    if (warp >= n_ent) return;

    const int start = g_row_start[warp];
    const int end   = g_row_start[warp + 1];

    float4 acc = make_float4(0.f, 0.f, 0.f, 0.f);

    int k = start;
    while (k < end) {
        int rem = end - k;
        unsigned myv = 0;
        if (lane < rem) myv = g_csr[k + lane];   // 1 LDG covers <=32 edges
        int batch = (rem < 32) ? rem : 32;

        int u = 0;
        for (; u + 7 < batch; u += 8) {
            unsigned v[8];
            uint2 p[8];
            #pragma unroll
            for (int t = 0; t < 8; t++)
                v[t] = __shfl_sync(0xFFFFFFFFu, myv, u + t);
            #pragma unroll
            for (int t = 0; t < 8; t++)
                p[t] = src[(v[t] & 0xFFFFFu) * C_H2V + lane];
            #pragma unroll
            for (int t = 0; t < 8; t++) {
                uint2 w = swh[(v[t] >> 20) * C_VEC + lane];
                float2 w0 = __half22float2(*(__half2*)&w.x);
                float2 w1 = __half22float2(*(__half2*)&w.y);
                float2 f0 = __half22float2(*(__half2*)&p[t].x);
                float2 f1 = __half22float2(*(__half2*)&p[t].y);
                acc.x += f0.x * w0.x; acc.y += f0.y * w0.y;
                acc.z += f1.x * w1.x; acc.w += f1.y * w1.y;
            }
        }
        for (; u < batch; u++) {
            unsigned v = __shfl_sync(0xFFFFFFFFu, myv, u);
            uint2 p = src[(v & 0xFFFFFu) * C_H2V + lane];
            uint2 w = swh[(v >> 20) * C_VEC + lane];
            float2 w0 = __half22float2(*(__half2*)&w.x);
            float2 w1 = __half22float2(*(__half2*)&w.y);
            float2 f0 = __half22float2(*(__half2*)&p.x);
            float2 f1 = __half22float2(*(__half2*)&p.y);
            acc.x += f0.x * w0.x; acc.y += f0.y * w0.y;
            acc.z += f1.x * w1.x; acc.w += f1.y * w1.y;
        }
        k += batch;
    }

    // scatter_mean
    float inv = 1.0f / fmaxf((float)(end - start), 1.0f);
    acc.x *= inv; acc.y *= inv; acc.z *= inv; acc.w *= inv;

    // L2 norm across 128 channels
    float ss = acc.x * acc.x + acc.y * acc.y + acc.z * acc.z + acc.w * acc.w;
    #pragma unroll
    for (int off = 16; off > 0; off >>= 1)
        ss += __shfl_xor_sync(0xFFFFFFFFu, ss, off);
    float scale = 1.0f / fmaxf(sqrtf(ss), 1e-12f);

    float4 o = make_float4(acc.x * scale, acc.y * scale,
                           acc.z * scale, acc.w * scale);

    int idx = warp * C_H2V + lane;

    if (hop < 2) {
        uint2* dst = (hop == 0) ? (uint2*)g_embA : (uint2*)g_embB;
        __half2 ha = __floats2half2_rn(o.x, o.y);
        __half2 hb = __floats2half2_rn(o.z, o.w);
        uint2 q;
        q.x = *(unsigned*)&ha;
        q.y = *(unsigned*)&hb;
        dst[idx] = q;
    } else {
        // fused finish: res = entity_emb + h1 + h2 + h3
        float4 r = emb32[idx];
        uint2 a = g_embA[idx];
        uint2 b = g_embB[idx];
        float2 ax = __half22float2(*(__half2*)&a.x);
        float2 ay = __half22float2(*(__half2*)&a.y);
        float2 bx = __half22float2(*(__half2*)&b.x);
        float2 by = __half22float2(*(__half2*)&b.y);
        r.x += ax.x + bx.x + o.x;
        r.y += ax.y + bx.y + o.y;
        r.z += ay.x + by.x + o.z;
        r.w += ay.y + by.y + o.w;
        res[idx] = r;
    }
}

// ---------------------------------------------------------------------------
extern "C" void kernel_launch(void* const* d_in, const int* in_sizes, int n_in,
                              void* d_out, int out_size) {
    const float*  entity_emb = (const float*)d_in[0];
    const void*   edge_index = d_in[1];
    const void*   edge_type  = d_in[2];
    const float*  weight     = (const float*)d_in[3];

    const int n_ent = in_sizes[0] / C_DIM;     // 50000
    const int E     = in_sizes[2];             // 1600000
    const int n_rel = in_sizes[3] / C_DIM;     // 10

    const int TB = 256;
    const int n_vec = n_ent * C_VEC;

    // CSR build + fp16 convert (once per launch; reused across the 3 hops)
    init_convert_kernel<<<(n_vec + TB - 1) / TB, TB>>>(
        (const unsigned*)edge_index, (const float4*)entity_emb, n_ent, n_vec);
    build_a_kernel<<<(E + TB - 1) / TB, TB>>>(edge_index, edge_type, E);
    scan_kernel<<<1, 1024>>>(n_ent);
    build_b_kernel<<<(E + TB - 1) / TB, TB>>>(E);

    // 3 fused hops, one warp per entity (8 warps/block); hop 2 also writes res
    const int hop_blocks = (n_ent * 32 + TB - 1) / TB;
    hop_kernel<<<hop_blocks, TB>>>((const float4*)weight,
                                   (const float4*)entity_emb,
                                   (float4*)d_out, n_ent, n_rel, 0);
    hop_kernel<<<hop_blocks, TB>>>((const float4*)weight,
                                   (const float4*)entity_emb,
                                   (float4*)d_out, n_ent, n_rel, 1);
    hop_kernel<<<hop_blocks, TB>>>((const float4*)weight,
                                   (const float4*)entity_emb,
                                   (float4*)d_out, n_ent, n_rel, 2);
}

// round 8
// speedup vs baseline: 1.0414x; 1.0414x over previous
#include <cuda_runtime.h>
#include <cuda_fp16.h>
#include <cstdint>

#define MAX_ENT   50000
#define MAX_E     1600000
#define MAX_REL   10       // N_REL - 1
#define C_DIM     128
#define C_VEC     (C_DIM / 4)    // 32 float4 per fp32 row
#define C_H2V     (C_DIM / 4)    // 32 uint2 (4 halves) per fp16 row

// ---------------- device scratch (static globals: no allocation allowed) ----
__device__ int            g_is64;
__device__ int            g_head[MAX_E];
__device__ unsigned short g_rank[MAX_E];     // within-head slot from histogram
__device__ unsigned       g_val[MAX_E];      // packed tail | (rel<<20)
__device__ unsigned       g_csr[MAX_E];      // CSR values: packed tail|rel
__device__ int            g_cnt[MAX_ENT];
__device__ int            g_row_start[MAX_ENT + 1];
__device__ uint2          g_embH[MAX_ENT * C_H2V];  // fp16 input embeddings
__device__ uint2          g_embA[MAX_ENT * C_H2V];  // fp16 hop-1 output
__device__ uint2          g_embB[MAX_ENT * C_H2V];  // fp16 hop-2 output

// ---------------------------------------------------------------------------
// 0) fused: zero per-head counters + fp32->fp16 embedding convert + width
//    detection.  (int64 ids < 2^31 have all odd 32-bit words zero; effectively
//    impossible for the int32 interpretation of random ids in [0,50000).)
__global__ void init_convert_kernel(const unsigned* __restrict__ words,
                                    const float4* __restrict__ emb,
                                    int n_ent, int n_vec) {
    int i = blockIdx.x * blockDim.x + threadIdx.x;
    if (i < n_ent) g_cnt[i] = 0;
    if (i < n_vec) {
        float4 f = emb[i];
        __half2 a = __floats2half2_rn(f.x, f.y);
        __half2 b = __floats2half2_rn(f.z, f.w);
        uint2 q;
        q.x = *(unsigned*)&a;
        q.y = *(unsigned*)&b;
        g_embH[i] = q;
    }
    if (i == 0) {
        int is64 = 1;
        #pragma unroll 1
        for (int k = 1; k < 64; k += 2) {     // 32 odd-word checks suffice
            if (words[k] != 0u) { is64 = 0; break; }
        }
        g_is64 = is64;
    }
}

// 1) decode edges, histogram head degrees, record within-head rank
__global__ void build_a_kernel(const void* __restrict__ edge_index,
                               const void* __restrict__ edge_type, int E) {
    int j = blockIdx.x * blockDim.x + threadIdx.x;
    if (j >= E) return;
    int head, tail, rel;
    if (g_is64) {
        const long long* ei = (const long long*)edge_index;
        const long long* et = (const long long*)edge_type;
        head = (int)ei[j];
        tail = (int)ei[E + j];
        rel  = (int)et[j] - 1;
    } else {
        const int* ei = (const int*)edge_index;
        const int* et = (const int*)edge_type;
        head = ei[j];
        tail = ei[E + j];
        rel  = et[j] - 1;
    }
    g_head[j] = head;
    g_val[j]  = (unsigned)tail | ((unsigned)rel << 20);
    int r = atomicAdd(&g_cnt[head], 1);
    g_rank[j] = (unsigned short)r;           // degrees ~Poisson(32) << 65536
}

// 2) exclusive scan of g_cnt -> g_row_start.  Single block, 1024 threads.
__global__ void scan_kernel(int n_ent) {
    __shared__ int ssum[1024];
    const int t    = threadIdx.x;
    const int PER  = (n_ent + 1023) / 1024;
    const int base = t * PER;

    int s = 0;
    for (int i = 0; i < PER; i++) {
        int idx = base + i;
        if (idx < n_ent) s += g_cnt[idx];
    }
    ssum[t] = s;
    __syncthreads();
    for (int off = 1; off < 1024; off <<= 1) {
        int v = (t >= off) ? ssum[t - off] : 0;
        __syncthreads();
        ssum[t] += v;
        __syncthreads();
    }
    int run = ssum[t] - s;
    for (int i = 0; i < PER; i++) {
        int idx = base + i;
        if (idx < n_ent) {
            g_row_start[idx] = run;
            run += g_cnt[idx];
        }
    }
    if (t == 1023) g_row_start[n_ent] = ssum[1023];
}

// 3) fill CSR values -- atomic-free: pos = row_start[head] + rank
__global__ void build_b_kernel(int E) {
    int j = blockIdx.x * blockDim.x + threadIdx.x;
    if (j >= E) return;
    int pos = g_row_start[g_head[j]] + (int)g_rank[j];
    g_csr[pos] = g_val[j];
}

// 4) fused hop: fp16 gather + relation scale + mean + L2-normalize.
//    One warp per entity; scalar (warp-uniform) CSR loads; fp32 weights in
//    smem.  8-wide unroll (proven R3/R5 loop body).
//    hop 0: src embH -> dst embA.   hop 1: embA -> embB.
//    hop 2: embB -> res = emb32 + h1 + h2 + h3  (fused finish).
__global__ __launch_bounds__(256)
void hop_kernel(const float4* __restrict__ weight,
                const float4* __restrict__ emb32,
                float4* __restrict__ res,
                int n_ent, int n_rel, int hop) {
    __shared__ float4 sw[MAX_REL * C_VEC];   // 5 KB: all relation rows fp32
    for (int i = threadIdx.x; i < n_rel * C_VEC; i += blockDim.x)
        sw[i] = weight[i];
    __syncthreads();

    const uint2* src = (hop == 0) ? (const uint2*)g_embH
                     : (hop == 1) ? (const uint2*)g_embA
                                  : (const uint2*)g_embB;

    int warp = (blockIdx.x * blockDim.x + threadIdx.x) >> 5;
    int lane = threadIdx.x & 31;
    if (warp >= n_ent) return;

    const int start = g_row_start[warp];
    const int end   = g_row_start[warp + 1];

    float4 acc = make_float4(0.f, 0.f, 0.f, 0.f);

    int k = start;
    // 8-wide unroll: 8 independent 64-bit gathers in flight per lane
    for (; k + 7 < end; k += 8) {
        unsigned v[8];
        uint2 p[8];
        #pragma unroll
        for (int u = 0; u < 8; u++) v[u] = g_csr[k + u];
        #pragma unroll
        for (int u = 0; u < 8; u++)
            p[u] = src[(v[u] & 0xFFFFFu) * C_H2V + lane];
        #pragma unroll
        for (int u = 0; u < 8; u++) {
            float4 w = sw[(v[u] >> 20) * C_VEC + lane];
            float2 fa = __half22float2(*(__half2*)&p[u].x);
            float2 fb = __half22float2(*(__half2*)&p[u].y);
            acc.x += fa.x * w.x; acc.y += fa.y * w.y;
            acc.z += fb.x * w.z; acc.w += fb.y * w.w;
        }
    }
    for (; k < end; k++) {
        unsigned v = g_csr[k];
        uint2 p = src[(v & 0xFFFFFu) * C_H2V + lane];
        float4 w = sw[(v >> 20) * C_VEC + lane];
        float2 fa = __half22float2(*(__half2*)&p.x);
        float2 fb = __half22float2(*(__half2*)&p.y);
        acc.x += fa.x * w.x; acc.y += fa.y * w.y;
        acc.z += fb.x * w.z; acc.w += fb.y * w.w;
    }

    // scatter_mean
    float inv = 1.0f / fmaxf((float)(end - start), 1.0f);
    acc.x *= inv; acc.y *= inv; acc.z *= inv; acc.w *= inv;

    // L2 norm across 128 channels
    float ss = acc.x * acc.x + acc.y * acc.y + acc.z * acc.z + acc.w * acc.w;
    #pragma unroll
    for (int off = 16; off > 0; off >>= 1)
        ss += __shfl_xor_sync(0xFFFFFFFFu, ss, off);
    float scale = 1.0f / fmaxf(sqrtf(ss), 1e-12f);

    float4 o = make_float4(acc.x * scale, acc.y * scale,
                           acc.z * scale, acc.w * scale);

    int idx = warp * C_H2V + lane;

    if (hop < 2) {
        uint2* dst = (hop == 0) ? (uint2*)g_embA : (uint2*)g_embB;
        __half2 ha = __floats2half2_rn(o.x, o.y);
        __half2 hb = __floats2half2_rn(o.z, o.w);
        uint2 q;
        q.x = *(unsigned*)&ha;
        q.y = *(unsigned*)&hb;
        dst[idx] = q;
    } else {
        // fused finish: res = entity_emb + h1 + h2 + h3
        float4 r = emb32[idx];
        uint2 a = g_embA[idx];
        uint2 b = g_embB[idx];
        float2 ax = __half22float2(*(__half2*)&a.x);
        float2 ay = __half22float2(*(__half2*)&a.y);
        float2 bx = __half22float2(*(__half2*)&b.x);
        float2 by = __half22float2(*(__half2*)&b.y);
        r.x += ax.x + bx.x + o.x;
        r.y += ax.y + bx.y + o.y;
        r.z += ay.x + by.x + o.z;
        r.w += ay.y + by.y + o.w;
        res[idx] = r;
    }
}

// ---------------------------------------------------------------------------
extern "C" void kernel_launch(void* const* d_in, const int* in_sizes, int n_in,
                              void* d_out, int out_size) {
    const float*  entity_emb = (const float*)d_in[0];
    const void*   edge_index = d_in[1];
    const void*   edge_type  = d_in[2];
    const float*  weight     = (const float*)d_in[3];

    const int n_ent = in_sizes[0] / C_DIM;     // 50000
    const int E     = in_sizes[2];             // 1600000
    const int n_rel = in_sizes[3] / C_DIM;     // 10

    const int TB = 256;
    const int n_vec = n_ent * C_VEC;

    // CSR build + fp16 convert (once per launch; reused across the 3 hops)
    init_convert_kernel<<<(n_vec + TB - 1) / TB, TB>>>(
        (const unsigned*)edge_index, (const float4*)entity_emb, n_ent, n_vec);
    build_a_kernel<<<(E + TB - 1) / TB, TB>>>(edge_index, edge_type, E);
    scan_kernel<<<1, 1024>>>(n_ent);
    build_b_kernel<<<(E + TB - 1) / TB, TB>>>(E);

    // 3 fused hops, one warp per entity (8 warps/block); hop 2 also writes res
    const int hop_blocks = (n_ent * 32 + TB - 1) / TB;
    hop_kernel<<<hop_blocks, TB>>>((const float4*)weight,
                                   (const float4*)entity_emb,
                                   (float4*)d_out, n_ent, n_rel, 0);
    hop_kernel<<<hop_blocks, TB>>>((const float4*)weight,
                                   (const float4*)entity_emb,
                                   (float4*)d_out, n_ent, n_rel, 1);
    hop_kernel<<<hop_blocks, TB>>>((const float4*)weight,
                                   (const float4*)entity_emb,
                                   (float4*)d_out, n_ent, n_rel, 2);
}

// round 9
// speedup vs baseline: 1.0546x; 1.0127x over previous
#include <cuda_runtime.h>
#include <cuda_fp16.h>
#include <cstdint>

#define MAX_ENT   50000
#define MAX_E     1600000
#define MAX_REL   10       // N_REL - 1
#define C_DIM     128
#define C_VEC     (C_DIM / 4)    // 32 float4 per fp32 row
#define C_H2V     (C_DIM / 4)    // 32 uint2 (4 halves) per fp16 row

// ---------------- device scratch (static globals: no allocation allowed) ----
__device__ int            g_is64;
__device__ int            g_head[MAX_E];
__device__ unsigned short g_rank[MAX_E];     // within-head slot from histogram
__device__ unsigned       g_val[MAX_E];      // packed tail | (rel<<20)
__device__ unsigned       g_csr[MAX_E];      // CSR values: packed tail|rel
__device__ int            g_cnt[MAX_ENT];
__device__ int            g_row_start[MAX_ENT + 1];
__device__ uint2          g_embH[MAX_ENT * C_H2V];  // fp16 input embeddings
__device__ uint2          g_embA[MAX_ENT * C_H2V];  // fp16 hop-1 output
__device__ uint2          g_embB[MAX_ENT * C_H2V];  // fp16 hop-2 output

// ---------------------------------------------------------------------------
// 0) fused: zero per-head counters + fp32->fp16 embedding convert + width
//    detection.  (int64 ids < 2^31 have all odd 32-bit words zero; effectively
//    impossible for the int32 interpretation of random ids in [0,50000).)
__global__ void init_convert_kernel(const unsigned* __restrict__ words,
                                    const float4* __restrict__ emb,
                                    int n_ent, int n_vec) {
    int i = blockIdx.x * blockDim.x + threadIdx.x;
    if (i < n_ent) g_cnt[i] = 0;
    if (i < n_vec) {
        float4 f = emb[i];
        __half2 a = __floats2half2_rn(f.x, f.y);
        __half2 b = __floats2half2_rn(f.z, f.w);
        uint2 q;
        q.x = *(unsigned*)&a;
        q.y = *(unsigned*)&b;
        g_embH[i] = q;
    }
    if (i == 0) {
        int is64 = 1;
        #pragma unroll 1
        for (int k = 1; k < 64; k += 2) {     // 32 odd-word checks suffice
            if (words[k] != 0u) { is64 = 0; break; }
        }
        g_is64 = is64;
    }
}

// 1) decode edges, histogram head degrees, record within-head rank
__global__ void build_a_kernel(const void* __restrict__ edge_index,
                               const void* __restrict__ edge_type, int E) {
    int j = blockIdx.x * blockDim.x + threadIdx.x;
    if (j >= E) return;
    int head, tail, rel;
    if (g_is64) {
        const long long* ei = (const long long*)edge_index;
        const long long* et = (const long long*)edge_type;
        head = (int)ei[j];
        tail = (int)ei[E + j];
        rel  = (int)et[j] - 1;
    } else {
        const int* ei = (const int*)edge_index;
        const int* et = (const int*)edge_type;
        head = ei[j];
        tail = ei[E + j];
        rel  = et[j] - 1;
    }
    g_head[j] = head;
    g_val[j]  = (unsigned)tail | ((unsigned)rel << 20);
    int r = atomicAdd(&g_cnt[head], 1);
    g_rank[j] = (unsigned short)r;           // degrees ~Poisson(32) << 65536
}

// 2) exclusive scan of g_cnt -> g_row_start.  Single block, 1024 threads.
__global__ void scan_kernel(int n_ent) {
    __shared__ int ssum[1024];
    const int t    = threadIdx.x;
    const int PER  = (n_ent + 1023) / 1024;
    const int base = t * PER;

    int s = 0;
    for (int i = 0; i < PER; i++) {
        int idx = base + i;
        if (idx < n_ent) s += g_cnt[idx];
    }
    ssum[t] = s;
    __syncthreads();
    for (int off = 1; off < 1024; off <<= 1) {
        int v = (t >= off) ? ssum[t - off] : 0;
        __syncthreads();
        ssum[t] += v;
        __syncthreads();
    }
    int run = ssum[t] - s;
    for (int i = 0; i < PER; i++) {
        int idx = base + i;
        if (idx < n_ent) {
            g_row_start[idx] = run;
            run += g_cnt[idx];
        }
    }
    if (t == 1023) g_row_start[n_ent] = ssum[1023];
}

// 3) fill CSR values -- atomic-free: pos = row_start[head] + rank
__global__ void build_b_kernel(int E) {
    int j = blockIdx.x * blockDim.x + threadIdx.x;
    if (j >= E) return;
    int pos = g_row_start[g_head[j]] + (int)g_rank[j];
    g_csr[pos] = g_val[j];
}

// 4) fused hop: fp16 gather + relation scale + mean + L2-normalize.
//    One warp per entity; scalar (warp-uniform) CSR loads; **fp16 weights in
//    smem (LDS.64, 2 crossbar phases/edge — the single change vs R8)**.
//    hop 0: src embH -> dst embA.   hop 1: embA -> embB.
//    hop 2: embB -> res = emb32 + h1 + h2 + h3  (fused finish).
__global__ __launch_bounds__(256)
void hop_kernel(const float4* __restrict__ weight,
                const float4* __restrict__ emb32,
                float4* __restrict__ res,
                int n_ent, int n_rel, int hop) {
    __shared__ uint2 swh[MAX_REL * C_VEC];   // 2.5 KB: fp16 relation rows
    for (int i = threadIdx.x; i < n_rel * C_VEC; i += blockDim.x) {
        float4 w = weight[i];
        __half2 a = __floats2half2_rn(w.x, w.y);
        __half2 b = __floats2half2_rn(w.z, w.w);
        uint2 q;
        q.x = *(unsigned*)&a;
        q.y = *(unsigned*)&b;
        swh[i] = q;
    }
    __syncthreads();

    const uint2* src = (hop == 0) ? (const uint2*)g_embH
                     : (hop == 1) ? (const uint2*)g_embA
                                  : (const uint2*)g_embB;

    int warp = (blockIdx.x * blockDim.x + threadIdx.x) >> 5;
    int lane = threadIdx.x & 31;
    if (warp >= n_ent) return;

    const int start = g_row_start[warp];
    const int end   = g_row_start[warp + 1];

    float4 acc = make_float4(0.f, 0.f, 0.f, 0.f);

    int k = start;
    // 8-wide unroll: 8 independent 64-bit gathers in flight per lane
    for (; k + 7 < end; k += 8) {
        unsigned v[8];
        uint2 p[8];
        #pragma unroll
        for (int u = 0; u < 8; u++) v[u] = g_csr[k + u];
        #pragma unroll
        for (int u = 0; u < 8; u++)
            p[u] = src[(v[u] & 0xFFFFFu) * C_H2V + lane];
        #pragma unroll
        for (int u = 0; u < 8; u++) {
            uint2 w = swh[(v[u] >> 20) * C_VEC + lane];
            float2 w0 = __half22float2(*(__half2*)&w.x);
            float2 w1 = __half22float2(*(__half2*)&w.y);
            float2 fa = __half22float2(*(__half2*)&p[u].x);
            float2 fb = __half22float2(*(__half2*)&p[u].y);
            acc.x += fa.x * w0.x; acc.y += fa.y * w0.y;
            acc.z += fb.x * w1.x; acc.w += fb.y * w1.y;
        }
    }
    for (; k < end; k++) {
        unsigned v = g_csr[k];
        uint2 p = src[(v & 0xFFFFFu) * C_H2V + lane];
        uint2 w = swh[(v >> 20) * C_VEC + lane];
        float2 w0 = __half22float2(*(__half2*)&w.x);
        float2 w1 = __half22float2(*(__half2*)&w.y);
        float2 fa = __half22float2(*(__half2*)&p.x);
        float2 fb = __half22float2(*(__half2*)&p.y);
        acc.x += fa.x * w0.x; acc.y += fa.y * w0.y;
        acc.z += fb.x * w1.x; acc.w += fb.y * w1.y;
    }

    // scatter_mean
    float inv = 1.0f / fmaxf((float)(end - start), 1.0f);
    acc.x *= inv; acc.y *= inv; acc.z *= inv; acc.w *= inv;

    // L2 norm across 128 channels
    float ss = acc.x * acc.x + acc.y * acc.y + acc.z * acc.z + acc.w * acc.w;
    #pragma unroll
    for (int off = 16; off > 0; off >>= 1)
        ss += __shfl_xor_sync(0xFFFFFFFFu, ss, off);
    float scale = 1.0f / fmaxf(sqrtf(ss), 1e-12f);

    float4 o = make_float4(acc.x * scale, acc.y * scale,
                           acc.z * scale, acc.w * scale);

    int idx = warp * C_H2V + lane;

    if (hop < 2) {
        uint2* dst = (hop == 0) ? (uint2*)g_embA : (uint2*)g_embB;
        __half2 ha = __floats2half2_rn(o.x, o.y);
        __half2 hb = __floats2half2_rn(o.z, o.w);
        uint2 q;
        q.x = *(unsigned*)&ha;
        q.y = *(unsigned*)&hb;
        dst[idx] = q;
    } else {
        // fused finish: res = entity_emb + h1 + h2 + h3
        float4 r = emb32[idx];
        uint2 a = g_embA[idx];
        uint2 b = g_embB[idx];
        float2 ax = __half22float2(*(__half2*)&a.x);
        float2 ay = __half22float2(*(__half2*)&a.y);
        float2 bx = __half22float2(*(__half2*)&b.x);
        float2 by = __half22float2(*(__half2*)&b.y);
        r.x += ax.x + bx.x + o.x;
        r.y += ax.y + bx.y + o.y;
        r.z += ay.x + by.x + o.z;
        r.w += ay.y + by.y + o.w;
        res[idx] = r;
    }
}

// ---------------------------------------------------------------------------
extern "C" void kernel_launch(void* const* d_in, const int* in_sizes, int n_in,
                              void* d_out, int out_size) {
    const float*  entity_emb = (const float*)d_in[0];
    const void*   edge_index = d_in[1];
    const void*   edge_type  = d_in[2];
    const float*  weight     = (const float*)d_in[3];

    const int n_ent = in_sizes[0] / C_DIM;     // 50000
    const int E     = in_sizes[2];             // 1600000
    const int n_rel = in_sizes[3] / C_DIM;     // 10

    const int TB = 256;
    const int n_vec = n_ent * C_VEC;

    // CSR build + fp16 convert (once per launch; reused across the 3 hops)
    init_convert_kernel<<<(n_vec + TB - 1) / TB, TB>>>(
        (const unsigned*)edge_index, (const float4*)entity_emb, n_ent, n_vec);
    build_a_kernel<<<(E + TB - 1) / TB, TB>>>(edge_index, edge_type, E);
    scan_kernel<<<1, 1024>>>(n_ent);
    build_b_kernel<<<(E + TB - 1) / TB, TB>>>(E);

    // 3 fused hops, one warp per entity (8 warps/block); hop 2 also writes res
    const int hop_blocks = (n_ent * 32 + TB - 1) / TB;
    hop_kernel<<<hop_blocks, TB>>>((const float4*)weight,
                                   (const float4*)entity_emb,
                                   (float4*)d_out, n_ent, n_rel, 0);
    hop_kernel<<<hop_blocks, TB>>>((const float4*)weight,
                                   (const float4*)entity_emb,
                                   (float4*)d_out, n_ent, n_rel, 1);
    hop_kernel<<<hop_blocks, TB>>>((const float4*)weight,
                                   (const float4*)entity_emb,
                                   (float4*)d_out, n_ent, n_rel, 2);
}

// round 11
// speedup vs baseline: 1.1536x; 1.0938x over previous
#include <cuda_runtime.h>
#include <cuda_fp16.h>
#include <cstdint>

#define MAX_ENT   50000
#define MAX_E     1600000
#define MAX_REL   10       // N_REL - 1
#define C_DIM     128
#define C_VEC     (C_DIM / 4)    // 32 float4 per fp32 row
#define C_H2V     (C_DIM / 4)    // 32 uint2 (4 halves) per fp16 row

// ---------------- device scratch (static globals: no allocation allowed) ----
__device__ int            g_is64;
__device__ int            g_head[MAX_E];
__device__ unsigned short g_rank[MAX_E];     // within-head slot from histogram
__device__ unsigned       g_val[MAX_E];      // packed tail | (rel<<20)
__device__ unsigned       g_csr[MAX_E];      // CSR values: packed tail|rel
__device__ int            g_cnt[MAX_ENT];
__device__ int            g_row_start[MAX_ENT + 1];
__device__ uint2          g_embH[MAX_ENT * C_H2V];  // fp16 input embeddings
__device__ uint2          g_embA[MAX_ENT * C_H2V];  // fp16 hop-1 output
__device__ uint2          g_embB[MAX_ENT * C_H2V];  // fp16 hop-2 output

// ---------------------------------------------------------------------------
// 0) fused: zero per-head counters + fp32->fp16 embedding convert + width
//    detection.  (int64 ids < 2^31 have all odd 32-bit words zero; effectively
//    impossible for the int32 interpretation of random ids in [0,50000).)
__global__ void init_convert_kernel(const unsigned* __restrict__ words,
                                    const float4* __restrict__ emb,
                                    int n_ent, int n_vec) {
    int i = blockIdx.x * blockDim.x + threadIdx.x;
    if (i < n_ent) g_cnt[i] = 0;
    if (i < n_vec) {
        float4 f = emb[i];
        __half2 a = __floats2half2_rn(f.x, f.y);
        __half2 b = __floats2half2_rn(f.z, f.w);
        uint2 q;
        q.x = *(unsigned*)&a;
        q.y = *(unsigned*)&b;
        g_embH[i] = q;
    }
    if (i == 0) {
        int is64 = 1;
        #pragma unroll 1
        for (int k = 1; k < 64; k += 2) {     // 32 odd-word checks suffice
            if (words[k] != 0u) { is64 = 0; break; }
        }
        g_is64 = is64;
    }
}

// 1) decode edges, histogram head degrees, record within-head rank
__global__ void build_a_kernel(const void* __restrict__ edge_index,
                               const void* __restrict__ edge_type, int E) {
    int j = blockIdx.x * blockDim.x + threadIdx.x;
    if (j >= E) return;
    int head, tail, rel;
    if (g_is64) {
        const long long* ei = (const long long*)edge_index;
        const long long* et = (const long long*)edge_type;
        head = (int)ei[j];
        tail = (int)ei[E + j];
        rel  = (int)et[j] - 1;
    } else {
        const int* ei = (const int*)edge_index;
        const int* et = (const int*)edge_type;
        head = ei[j];
        tail = ei[E + j];
        rel  = et[j] - 1;
    }
    g_head[j] = head;
    g_val[j]  = (unsigned)tail | ((unsigned)rel << 20);
    int r = atomicAdd(&g_cnt[head], 1);
    g_rank[j] = (unsigned short)r;           // degrees ~Poisson(32) << 65536
}

// 2) exclusive scan of g_cnt -> g_row_start.  Single block, 1024 threads.
__global__ void scan_kernel(int n_ent) {
    __shared__ int ssum[1024];
    const int t    = threadIdx.x;
    const int PER  = (n_ent + 1023) / 1024;
    const int base = t * PER;

    int s = 0;
    for (int i = 0; i < PER; i++) {
        int idx = base + i;
        if (idx < n_ent) s += g_cnt[idx];
    }
    ssum[t] = s;
    __syncthreads();
    for (int off = 1; off < 1024; off <<= 1) {
        int v = (t >= off) ? ssum[t - off] : 0;
        __syncthreads();
        ssum[t] += v;
        __syncthreads();
    }
    int run = ssum[t] - s;
    for (int i = 0; i < PER; i++) {
        int idx = base + i;
        if (idx < n_ent) {
            g_row_start[idx] = run;
            run += g_cnt[idx];
        }
    }
    if (t == 1023) g_row_start[n_ent] = ssum[1023];
}

// 3) fill CSR values -- atomic-free: pos = row_start[head] + rank
__global__ void build_b_kernel(int E) {
    int j = blockIdx.x * blockDim.x + threadIdx.x;
    if (j >= E) return;
    int pos = g_row_start[g_head[j]] + (int)g_rank[j];
    g_csr[pos] = g_val[j];
}

// 4) fused hop.  SINGLE CHANGE vs R9: inner-loop math is native half2 —
//    2 HFMA2 per edge (parity-split dual accumulators, fp32 combine at end)
//    replacing 4 H2F + 4 FFMA.  ~4.5 warp-instr/edge vs ~10.
//    hop 0: src embH -> dst embA.   hop 1: embA -> embB.
//    hop 2: embB -> res = emb32 + h1 + h2 + h3  (fused finish).
__global__ __launch_bounds__(256)
void hop_kernel(const float4* __restrict__ weight,
                const float4* __restrict__ emb32,
                float4* __restrict__ res,
                int n_ent, int n_rel, int hop) {
    __shared__ uint2 swh[MAX_REL * C_VEC];   // 2.5 KB: fp16 relation rows
    for (int i = threadIdx.x; i < n_rel * C_VEC; i += blockDim.x) {
        float4 w = weight[i];
        __half2 a = __floats2half2_rn(w.x, w.y);
        __half2 b = __floats2half2_rn(w.z, w.w);
        uint2 q;
        q.x = *(unsigned*)&a;
        q.y = *(unsigned*)&b;
        swh[i] = q;
    }
    __syncthreads();

    const uint2* src = (hop == 0) ? (const uint2*)g_embH
                     : (hop == 1) ? (const uint2*)g_embA
                                  : (const uint2*)g_embB;

    int warp = (blockIdx.x * blockDim.x + threadIdx.x) >> 5;
    int lane = threadIdx.x & 31;
    if (warp >= n_ent) return;

    const int start = g_row_start[warp];
    const int end   = g_row_start[warp + 1];

    const __half2 hz = __float2half2_rn(0.f);
    __half2 aA01 = hz, aA23 = hz;   // even-parity accumulators
    __half2 aB01 = hz, aB23 = hz;   // odd-parity accumulators

    int k = start;
    // 8-wide unroll: 8 independent 64-bit gathers in flight per lane
    for (; k + 7 < end; k += 8) {
        unsigned v[8];
        uint2 p[8];
        #pragma unroll
        for (int u = 0; u < 8; u++) v[u] = g_csr[k + u];
        #pragma unroll
        for (int u = 0; u < 8; u++)
            p[u] = src[(v[u] & 0xFFFFFu) * C_H2V + lane];
        #pragma unroll
        for (int u = 0; u < 8; u++) {
            uint2 w = swh[(v[u] >> 20) * C_VEC + lane];
            __half2 x01 = *(__half2*)&p[u].x;
            __half2 x23 = *(__half2*)&p[u].y;
            __half2 w01 = *(__half2*)&w.x;
            __half2 w23 = *(__half2*)&w.y;
            if (u & 1) {
                aB01 = __hfma2(x01, w01, aB01);
                aB23 = __hfma2(x23, w23, aB23);
            } else {
                aA01 = __hfma2(x01, w01, aA01);
                aA23 = __hfma2(x23, w23, aA23);
            }
        }
    }
    for (; k < end; k++) {
        unsigned v = g_csr[k];
        uint2 p = src[(v & 0xFFFFFu) * C_H2V + lane];
        uint2 w = swh[(v >> 20) * C_VEC + lane];
        __half2 x01 = *(__half2*)&p.x;
        __half2 x23 = *(__half2*)&p.y;
        __half2 w01 = *(__half2*)&w.x;
        __half2 w23 = *(__half2*)&w.y;
        if (k & 1) {
            aB01 = __hfma2(x01, w01, aB01);
            aB23 = __hfma2(x23, w23, aB23);
        } else {
            aA01 = __hfma2(x01, w01, aA01);
            aA23 = __hfma2(x23, w23, aA23);
        }
    }

    // fp32 combine of the two half2 partial sums
    float2 fA01 = __half22float2(aA01), fB01 = __half22float2(aB01);
    float2 fA23 = __half22float2(aA23), fB23 = __half22float2(aB23);
    float4 acc = make_float4(fA01.x + fB01.x, fA01.y + fB01.y,
                             fA23.x + fB23.x, fA23.y + fB23.y);

    // scatter_mean
    float inv = 1.0f / fmaxf((float)(end - start), 1.0f);
    acc.x *= inv; acc.y *= inv; acc.z *= inv; acc.w *= inv;

    // L2 norm across 128 channels
    float ss = acc.x * acc.x + acc.y * acc.y + acc.z * acc.z + acc.w * acc.w;
    #pragma unroll
    for (int off = 16; off > 0; off >>= 1)
        ss += __shfl_xor_sync(0xFFFFFFFFu, ss, off);
    float scale = 1.0f / fmaxf(sqrtf(ss), 1e-12f);

    float4 o = make_float4(acc.x * scale, acc.y * scale,
                           acc.z * scale, acc.w * scale);

    int idx = warp * C_H2V + lane;

    if (hop < 2) {
        uint2* dst = (hop == 0) ? (uint2*)g_embA : (uint2*)g_embB;
        __half2 ha = __floats2half2_rn(o.x, o.y);
        __half2 hb = __floats2half2_rn(o.z, o.w);
        uint2 q;
        q.x = *(unsigned*)&ha;
        q.y = *(unsigned*)&hb;
        dst[idx] = q;
    } else {
        // fused finish: res = entity_emb + h1 + h2 + h3
        float4 r = emb32[idx];
        uint2 a = g_embA[idx];
        uint2 b = g_embB[idx];
        float2 ax = __half22float2(*(__half2*)&a.x);
        float2 ay = __half22float2(*(__half2*)&a.y);
        float2 bx = __half22float2(*(__half2*)&b.x);
        float2 by = __half22float2(*(__half2*)&b.y);
        r.x += ax.x + bx.x + o.x;
        r.y += ax.y + bx.y + o.y;
        r.z += ay.x + by.x + o.z;
        r.w += ay.y + by.y + o.w;
        res[idx] = r;
    }
}

// ---------------------------------------------------------------------------
extern "C" void kernel_launch(void* const* d_in, const int* in_sizes, int n_in,
                              void* d_out, int out_size) {
    const float*  entity_emb = (const float*)d_in[0];
    const void*   edge_index = d_in[1];
    const void*   edge_type  = d_in[2];
    const float*  weight     = (const float*)d_in[3];

    const int n_ent = in_sizes[0] / C_DIM;     // 50000
    const int E     = in_sizes[2];             // 1600000
    const int n_rel = in_sizes[3] / C_DIM;     // 10

    const int TB = 256;
    const int n_vec = n_ent * C_VEC;

    // CSR build + fp16 convert (once per launch; reused across the 3 hops)
    init_convert_kernel<<<(n_vec + TB - 1) / TB, TB>>>(
        (const unsigned*)edge_index, (const float4*)entity_emb, n_ent, n_vec);
    build_a_kernel<<<(E + TB - 1) / TB, TB>>>(edge_index, edge_type, E);
    scan_kernel<<<1, 1024>>>(n_ent);
    build_b_kernel<<<(E + TB - 1) / TB, TB>>>(E);

    // 3 fused hops, one warp per entity (8 warps/block); hop 2 also writes res
    const int hop_blocks = (n_ent * 32 + TB - 1) / TB;
    hop_kernel<<<hop_blocks, TB>>>((const float4*)weight,
                                   (const float4*)entity_emb,
                                   (float4*)d_out, n_ent, n_rel, 0);
    hop_kernel<<<hop_blocks, TB>>>((const float4*)weight,
                                   (const float4*)entity_emb,
                                   (float4*)d_out, n_ent, n_rel, 1);
    hop_kernel<<<hop_blocks, TB>>>((const float4*)weight,
                                   (const float4*)entity_emb,
                                   (float4*)d_out, n_ent, n_rel, 2);
}

// round 12
// speedup vs baseline: 1.2114x; 1.0502x over previous
#include <cuda_runtime.h>
#include <cuda_fp16.h>
#include <cstdint>

#define MAX_ENT   50000
#define MAX_E     1600000
#define MAX_REL   10       // N_REL - 1
#define C_DIM     128
#define C_VEC     (C_DIM / 4)    // 32 float4 per fp32 row
#define C_H2V     (C_DIM / 4)    // 32 uint2 (4 halves) per fp16 row

// ---------------- device scratch (static globals: no allocation allowed) ----
__device__ int            g_is64;
__device__ int            g_head[MAX_E];
__device__ unsigned short g_rank[MAX_E];     // within-head slot from histogram
__device__ unsigned       g_val[MAX_E];      // packed tail | (rel<<20)
__device__ unsigned       g_csr[MAX_E];      // CSR values: packed tail|rel
__device__ int            g_cnt[MAX_ENT];
__device__ int            g_row_start[MAX_ENT + 1];
__device__ uint2          g_embH[MAX_ENT * C_H2V];  // fp16 input embeddings
__device__ uint2          g_embA[MAX_ENT * C_H2V];  // fp16 hop-1 output
__device__ uint2          g_embB[MAX_ENT * C_H2V];  // fp16 hop-2 output

// ---------------------------------------------------------------------------
// 0) fused: zero per-head counters + fp32->fp16 embedding convert + width
//    detection.  (int64 ids < 2^31 have all odd 32-bit words zero; effectively
//    impossible for the int32 interpretation of random ids in [0,50000).)
__global__ void init_convert_kernel(const unsigned* __restrict__ words,
                                    const float4* __restrict__ emb,
                                    int n_ent, int n_vec) {
    int i = blockIdx.x * blockDim.x + threadIdx.x;
    if (i < n_ent) g_cnt[i] = 0;
    if (i < n_vec) {
        float4 f = emb[i];
        __half2 a = __floats2half2_rn(f.x, f.y);
        __half2 b = __floats2half2_rn(f.z, f.w);
        uint2 q;
        q.x = *(unsigned*)&a;
        q.y = *(unsigned*)&b;
        g_embH[i] = q;
    }
    if (i == 0) {
        int is64 = 1;
        #pragma unroll 1
        for (int k = 1; k < 64; k += 2) {     // 32 odd-word checks suffice
            if (words[k] != 0u) { is64 = 0; break; }
        }
        g_is64 = is64;
    }
}

// 1) decode edges, histogram head degrees, record within-head rank
__global__ void build_a_kernel(const void* __restrict__ edge_index,
                               const void* __restrict__ edge_type, int E) {
    int j = blockIdx.x * blockDim.x + threadIdx.x;
    if (j >= E) return;
    int head, tail, rel;
    if (g_is64) {
        const long long* ei = (const long long*)edge_index;
        const long long* et = (const long long*)edge_type;
        head = (int)ei[j];
        tail = (int)ei[E + j];
        rel  = (int)et[j] - 1;
    } else {
        const int* ei = (const int*)edge_index;
        const int* et = (const int*)edge_type;
        head = ei[j];
        tail = ei[E + j];
        rel  = et[j] - 1;
    }
    g_head[j] = head;
    g_val[j]  = (unsigned)tail | ((unsigned)rel << 20);
    int r = atomicAdd(&g_cnt[head], 1);
    g_rank[j] = (unsigned short)r;           // degrees ~Poisson(32) << 65536
}

// 2) exclusive scan of g_cnt -> g_row_start.  Single block, 1024 threads.
__global__ void scan_kernel(int n_ent) {
    __shared__ int ssum[1024];
    const int t    = threadIdx.x;
    const int PER  = (n_ent + 1023) / 1024;
    const int base = t * PER;

    int s = 0;
    for (int i = 0; i < PER; i++) {
        int idx = base + i;
        if (idx < n_ent) s += g_cnt[idx];
    }
    ssum[t] = s;
    __syncthreads();
    for (int off = 1; off < 1024; off <<= 1) {
        int v = (t >= off) ? ssum[t - off] : 0;
        __syncthreads();
        ssum[t] += v;
        __syncthreads();
    }
    int run = ssum[t] - s;
    for (int i = 0; i < PER; i++) {
        int idx = base + i;
        if (idx < n_ent) {
            g_row_start[idx] = run;
            run += g_cnt[idx];
        }
    }
    if (t == 1023) g_row_start[n_ent] = ssum[1023];
}

// 3) fill CSR values -- atomic-free: pos = row_start[head] + rank
__global__ void build_b_kernel(int E) {
    int j = blockIdx.x * blockDim.x + threadIdx.x;
    if (j >= E) return;
    int pos = g_row_start[g_head[j]] + (int)g_rank[j];
    g_csr[pos] = g_val[j];
}

// 4) fused hop.  SINGLE CHANGE vs R11: 16-wide unrolled gather batch
//    (16 outstanding uint2 gathers per lane instead of 8) to deepen the
//    L2 pipeline.  Math body identical (HFMA2, parity-split accumulators).
//    hop 0: src embH -> dst embA.   hop 1: embA -> embB.
//    hop 2: embB -> res = emb32 + h1 + h2 + h3  (fused finish).
__global__ __launch_bounds__(256)
void hop_kernel(const float4* __restrict__ weight,
                const float4* __restrict__ emb32,
                float4* __restrict__ res,
                int n_ent, int n_rel, int hop) {
    __shared__ uint2 swh[MAX_REL * C_VEC];   // 2.5 KB: fp16 relation rows
    for (int i = threadIdx.x; i < n_rel * C_VEC; i += blockDim.x) {
        float4 w = weight[i];
        __half2 a = __floats2half2_rn(w.x, w.y);
        __half2 b = __floats2half2_rn(w.z, w.w);
        uint2 q;
        q.x = *(unsigned*)&a;
        q.y = *(unsigned*)&b;
        swh[i] = q;
    }
    __syncthreads();

    const uint2* src = (hop == 0) ? (const uint2*)g_embH
                     : (hop == 1) ? (const uint2*)g_embA
                                  : (const uint2*)g_embB;

    int warp = (blockIdx.x * blockDim.x + threadIdx.x) >> 5;
    int lane = threadIdx.x & 31;
    if (warp >= n_ent) return;

    const int start = g_row_start[warp];
    const int end   = g_row_start[warp + 1];

    const __half2 hz = __float2half2_rn(0.f);
    __half2 aA01 = hz, aA23 = hz;   // even-parity accumulators
    __half2 aB01 = hz, aB23 = hz;   // odd-parity accumulators

    int k = start;
    // 16-wide unroll: 16 independent 64-bit gathers in flight per lane
    for (; k + 15 < end; k += 16) {
        unsigned v[16];
        uint2 p[16];
        #pragma unroll
        for (int u = 0; u < 16; u++) v[u] = g_csr[k + u];
        #pragma unroll
        for (int u = 0; u < 16; u++)
            p[u] = src[(v[u] & 0xFFFFFu) * C_H2V + lane];
        #pragma unroll
        for (int u = 0; u < 16; u++) {
            uint2 w = swh[(v[u] >> 20) * C_VEC + lane];
            __half2 x01 = *(__half2*)&p[u].x;
            __half2 x23 = *(__half2*)&p[u].y;
            __half2 w01 = *(__half2*)&w.x;
            __half2 w23 = *(__half2*)&w.y;
            if (u & 1) {
                aB01 = __hfma2(x01, w01, aB01);
                aB23 = __hfma2(x23, w23, aB23);
            } else {
                aA01 = __hfma2(x01, w01, aA01);
                aA23 = __hfma2(x23, w23, aA23);
            }
        }
    }
    // 8-wide cleanup
    for (; k + 7 < end; k += 8) {
        unsigned v[8];
        uint2 p[8];
        #pragma unroll
        for (int u = 0; u < 8; u++) v[u] = g_csr[k + u];
        #pragma unroll
        for (int u = 0; u < 8; u++)
            p[u] = src[(v[u] & 0xFFFFFu) * C_H2V + lane];
        #pragma unroll
        for (int u = 0; u < 8; u++) {
            uint2 w = swh[(v[u] >> 20) * C_VEC + lane];
            __half2 x01 = *(__half2*)&p[u].x;
            __half2 x23 = *(__half2*)&p[u].y;
            __half2 w01 = *(__half2*)&w.x;
            __half2 w23 = *(__half2*)&w.y;
            if (u & 1) {
                aB01 = __hfma2(x01, w01, aB01);
                aB23 = __hfma2(x23, w23, aB23);
            } else {
                aA01 = __hfma2(x01, w01, aA01);
                aA23 = __hfma2(x23, w23, aA23);
            }
        }
    }
    for (; k < end; k++) {
        unsigned v = g_csr[k];
        uint2 p = src[(v & 0xFFFFFu) * C_H2V + lane];
        uint2 w = swh[(v >> 20) * C_VEC + lane];
        __half2 x01 = *(__half2*)&p.x;
        __half2 x23 = *(__half2*)&p.y;
        __half2 w01 = *(__half2*)&w.x;
        __half2 w23 = *(__half2*)&w.y;
        if (k & 1) {
            aB01 = __hfma2(x01, w01, aB01);
            aB23 = __hfma2(x23, w23, aB23);
        } else {
            aA01 = __hfma2(x01, w01, aA01);
            aA23 = __hfma2(x23, w23, aA23);
        }
    }

    // fp32 combine of the two half2 partial sums
    float2 fA01 = __half22float2(aA01), fB01 = __half22float2(aB01);
    float2 fA23 = __half22float2(aA23), fB23 = __half22float2(aB23);
    float4 acc = make_float4(fA01.x + fB01.x, fA01.y + fB01.y,
                             fA23.x + fB23.x, fA23.y + fB23.y);

    // scatter_mean
    float inv = 1.0f / fmaxf((float)(end - start), 1.0f);
    acc.x *= inv; acc.y *= inv; acc.z *= inv; acc.w *= inv;

    // L2 norm across 128 channels
    float ss = acc.x * acc.x + acc.y * acc.y + acc.z * acc.z + acc.w * acc.w;
    #pragma unroll
    for (int off = 16; off > 0; off >>= 1)
        ss += __shfl_xor_sync(0xFFFFFFFFu, ss, off);
    float scale = 1.0f / fmaxf(sqrtf(ss), 1e-12f);

    float4 o = make_float4(acc.x * scale, acc.y * scale,
                           acc.z * scale, acc.w * scale);

    int idx = warp * C_H2V + lane;

    if (hop < 2) {
        uint2* dst = (hop == 0) ? (uint2*)g_embA : (uint2*)g_embB;
        __half2 ha = __floats2half2_rn(o.x, o.y);
        __half2 hb = __floats2half2_rn(o.z, o.w);
        uint2 q;
        q.x = *(unsigned*)&ha;
        q.y = *(unsigned*)&hb;
        dst[idx] = q;
    } else {
        // fused finish: res = entity_emb + h1 + h2 + h3
        float4 r = emb32[idx];
        uint2 a = g_embA[idx];
        uint2 b = g_embB[idx];
        float2 ax = __half22float2(*(__half2*)&a.x);
        float2 ay = __half22float2(*(__half2*)&a.y);
        float2 bx = __half22float2(*(__half2*)&b.x);
        float2 by = __half22float2(*(__half2*)&b.y);
        r.x += ax.x + bx.x + o.x;
        r.y += ax.y + bx.y + o.y;
        r.z += ay.x + by.x + o.z;
        r.w += ay.y + by.y + o.w;
        res[idx] = r;
    }
}

// ---------------------------------------------------------------------------
extern "C" void kernel_launch(void* const* d_in, const int* in_sizes, int n_in,
                              void* d_out, int out_size) {
    const float*  entity_emb = (const float*)d_in[0];
    const void*   edge_index = d_in[1];
    const void*   edge_type  = d_in[2];
    const float*  weight     = (const float*)d_in[3];

    const int n_ent = in_sizes[0] / C_DIM;     // 50000
    const int E     = in_sizes[2];             // 1600000
    const int n_rel = in_sizes[3] / C_DIM;     // 10

    const int TB = 256;
    const int n_vec = n_ent * C_VEC;

    // CSR build + fp16 convert (once per launch; reused across the 3 hops)
    init_convert_kernel<<<(n_vec + TB - 1) / TB, TB>>>(
        (const unsigned*)edge_index, (const float4*)entity_emb, n_ent, n_vec);
    build_a_kernel<<<(E + TB - 1) / TB, TB>>>(edge_index, edge_type, E);
    scan_kernel<<<1, 1024>>>(n_ent);
    build_b_kernel<<<(E + TB - 1) / TB, TB>>>(E);

    // 3 fused hops, one warp per entity (8 warps/block); hop 2 also writes res
    const int hop_blocks = (n_ent * 32 + TB - 1) / TB;
    hop_kernel<<<hop_blocks, TB>>>((const float4*)weight,
                                   (const float4*)entity_emb,
                                   (float4*)d_out, n_ent, n_rel, 0);
    hop_kernel<<<hop_blocks, TB>>>((const float4*)weight,
                                   (const float4*)entity_emb,
                                   (float4*)d_out, n_ent, n_rel, 1);
    hop_kernel<<<hop_blocks, TB>>>((const float4*)weight,
                                   (const float4*)entity_emb,
                                   (float4*)d_out, n_ent, n_rel, 2);
}